// round 16
// baseline (speedup 1.0000x reference)
#include <cuda_runtime.h>

#define F_CH    64
#define HW      4096
#define BATCH   32
#define NSTAT   14
#define GSIZE   64            // blocks per channel: 32 batches x 2 half-planes
#define FPR     4             // channels per round
#define NBLK    (FPR * GSIZE) // 256 persistent blocks, single wave
#define ITERS   (F_CH / FPR)  // 16 rounds
#define HALFN   2048          // floats per half-plane
#define BUF_FLT (4 * HALFN)   // 8192 floats = 32 KB per buffer

__device__ float g_part[F_CH * GSIZE * NSTAT];
__device__ unsigned int g_cnt[F_CH];   // monotonic tickets (zero-init)

__device__ __forceinline__ unsigned int ld_acq(const unsigned int* p) {
    unsigned int v;
    asm volatile("ld.acquire.gpu.global.u32 %0, [%1];" : "=r"(v) : "l"(p) : "memory");
    return v;
}
__device__ __forceinline__ void cp16(unsigned int saddr, const float* g) {
    asm volatile("cp.async.cg.shared.global [%0], [%1], 16;" :: "r"(saddr), "l"(g));
}
__device__ __forceinline__ void st_wt4(float4* p, float4 v) {
    asm volatile("st.global.wt.v4.f32 [%0], {%1,%2,%3,%4};"
                 :: "l"(p), "f"(v.x), "f"(v.y), "f"(v.z), "f"(v.w) : "memory");
}

__device__ __forceinline__ void acc4(float x0, float x1, float x2, float x3, float* s) {
    s[0] += x0; s[1] += x1; s[2] += x2; s[3] += x3;
    s[4]  = fmaf(x0, x0, s[4]);
    s[5]  = fmaf(x0, x1, s[5]);
    s[6]  = fmaf(x0, x2, s[6]);
    s[7]  = fmaf(x0, x3, s[7]);
    s[8]  = fmaf(x1, x1, s[8]);
    s[9]  = fmaf(x1, x2, s[9]);
    s[10] = fmaf(x1, x3, s[10]);
    s[11] = fmaf(x2, x3, s[11]);
    s[12] = fmaf(x2, x2, s[12]);
    s[13] = fmaf(x3, x3, s[13]);
}
// s: 0..3 sums; 4:00 5:01 6:02 7:03 8:11 9:12 10:13 11:23 12:22 13:33

__device__ __forceinline__ float4 mix4(float4 v0, float4 v1, float4 v2, float4 v3,
                                       float w0, float w1, float w2, float w3, float bb) {
    float4 o;
    o.x = fmaf(w0, v0.x, fmaf(w1, v1.x, fmaf(w2, v2.x, fmaf(w3, v3.x, bb))));
    o.y = fmaf(w0, v0.y, fmaf(w1, v1.y, fmaf(w2, v2.y, fmaf(w3, v3.y, bb))));
    o.z = fmaf(w0, v0.z, fmaf(w1, v1.z, fmaf(w2, v2.z, fmaf(w3, v3.z, bb))));
    o.w = fmaf(w0, v0.w, fmaf(w1, v1.w, fmaf(w2, v2.w, fmaf(w3, v3.w, bb))));
    return o;
}

// Persistent fused kernel: x enters the SM exactly once (cp.async -> smem),
// both stats and apply read the smem tile -> LTS traffic = 268 MB, not 402.
__global__ __launch_bounds__(256) void fused_qbn(const float* __restrict__ x,
                                                 const float* __restrict__ weight,
                                                 const float* __restrict__ bias,
                                                 float* __restrict__ out) {
    const int f_loc = blockIdx.x >> 6;   // 0..3
    const int sub   = blockIdx.x & 63;   // 0..63
    const int bb    = sub >> 1;          // 0..31
    const int half  = sub & 1;           // 0..1

    extern __shared__ float dyn[];       // 2 x 32 KB tile buffers
    __shared__ float sm[8][NSTAT];
    __shared__ float AC[20];
    const int warp = threadIdx.x >> 5, lane = threadIdx.x & 31;
    const int i0 = threadIdx.x, i1 = threadIdx.x + 256;  // float4 idx in 512/plane

    // Issue one half-plane tile's loads (32 KB) for channel f into buf; commit.
    auto issue = [&](int f, float* buf) {
        const size_t base = ((size_t)bb * 256 + f) * HW + (size_t)half * HALFN;
        unsigned int s0 = (unsigned int)__cvta_generic_to_shared(buf);
#pragma unroll
        for (int p = 0; p < 4; p++) {
            const float* gp = x + base + (size_t)p * 64 * HW;
#pragma unroll
            for (int j = 0; j < 2; j++) {
                const int c = threadIdx.x + j * 256;        // 16B chunk 0..511
                cp16(s0 + (unsigned int)(p * HALFN + c * 4) * 4u, gp + c * 4);
            }
        }
        asm volatile("cp.async.commit_group;" ::: "memory");
    };

    issue(f_loc, dyn);   // prologue: round 0 -> buffer 0

    for (int it = 0; it < ITERS; it++) {
        const int f = it * FPR + f_loc;
        float* cur = dyn + (it & 1) * BUF_FLT;

        // Queue next round's tile BEFORE consuming this one: these cp.asyncs
        // stay in flight through the barrier spin below.
        if (it + 1 < ITERS) {
            issue((it + 1) * FPR + f_loc, dyn + ((it + 1) & 1) * BUF_FLT);
            asm volatile("cp.async.wait_group 1;" ::: "memory");   // cur done
        } else {
            asm volatile("cp.async.wait_group 0;" ::: "memory");
        }
        __syncthreads();

        // ---- stats from the smem tile ----
        const float4* b0 = (const float4*)cur;
        const float4* b1 = (const float4*)(cur + HALFN);
        const float4* b2 = (const float4*)(cur + 2 * HALFN);
        const float4* b3 = (const float4*)(cur + 3 * HALFN);
        float s[NSTAT];
#pragma unroll
        for (int k = 0; k < NSTAT; k++) s[k] = 0.f;
#pragma unroll
        for (int rep = 0; rep < 2; rep++) {
            const int i = (rep == 0) ? i0 : i1;
            float4 v0 = b0[i], v1 = b1[i], v2 = b2[i], v3 = b3[i];
            acc4(v0.x, v1.x, v2.x, v3.x, s);
            acc4(v0.y, v1.y, v2.y, v3.y, s);
            acc4(v0.z, v1.z, v2.z, v3.z, s);
            acc4(v0.w, v1.w, v2.w, v3.w, s);
        }
#pragma unroll
        for (int k = 0; k < NSTAT; k++) {
#pragma unroll
            for (int off = 16; off; off >>= 1)
                s[k] += __shfl_down_sync(0xffffffffu, s[k], off);
        }
        if (lane == 0) {
#pragma unroll
            for (int k = 0; k < NSTAT; k++) sm[warp][k] = s[k];
        }
        __syncthreads();
        if (threadIdx.x < NSTAT) {
            float v = 0.f;
#pragma unroll
            for (int w = 0; w < 8; w++) v += sm[w][threadIdx.x];
            g_part[(f * GSIZE + sub) * NSTAT + threadIdx.x] = v;
            __threadfence();                    // release partials
        }
        __syncthreads();
        if (threadIdx.x == 0) atomicAdd(&g_cnt[f], 1u);   // arrive

        // ---- spin: next round's cp.asyncs keep DRAM busy meanwhile ----
        if (threadIdx.x == 0) {
            while (ld_acq(&g_cnt[f]) & (GSIZE - 1)) { }
        }
        __syncthreads();

        // ---- redundant per-block solve ----
        if (threadIdx.x < 32) {
            float r[NSTAT];
            const float* pa = &g_part[(f * GSIZE + threadIdx.x) * NSTAT];
            const float* pb = &g_part[(f * GSIZE + threadIdx.x + 32) * NSTAT];
#pragma unroll
            for (int k = 0; k < NSTAT; k++) r[k] = __ldcg(&pa[k]) + __ldcg(&pb[k]);
#pragma unroll
            for (int k = 0; k < NSTAT; k++) {
#pragma unroll
                for (int off = 16; off; off >>= 1)
                    r[k] += __shfl_down_sync(0xffffffffu, r[k], off);
            }
            if (threadIdx.x == 0) {
                const float invN = 1.0f / (float)(BATCH * HW);
                const float eps = 1e-5f;
                float m0 = r[0] * invN, m1 = r[1] * invN, m2 = r[2] * invN, m3 = r[3] * invN;
                float c00 = r[4]  * invN - m0 * m0 + eps;
                float c10 = r[5]  * invN - m0 * m1;
                float c20 = r[6]  * invN - m0 * m2;
                float c30 = r[7]  * invN - m0 * m3;
                float c11 = r[8]  * invN - m1 * m1 + eps;
                float c21 = r[9]  * invN - m1 * m2;
                float c31 = r[10] * invN - m1 * m3;
                float c32 = r[11] * invN - m2 * m3;
                float c22 = r[12] * invN - m2 * m2 + eps;
                float c33 = r[13] * invN - m3 * m3 + eps;

                float L00 = sqrtf(c00);
                float L10 = c10 / L00, L20 = c20 / L00, L30 = c30 / L00;
                float L11 = sqrtf(c11 - L10 * L10);
                float L21 = (c21 - L20 * L10) / L11;
                float L31 = (c31 - L30 * L10) / L11;
                float L22 = sqrtf(c22 - L20 * L20 - L21 * L21);
                float L32 = (c32 - L30 * L20 - L31 * L21) / L22;
                float L33 = sqrtf(c33 - L30 * L30 - L31 * L31 - L32 * L32);

                float i00f = 1.f / L00, i11f = 1.f / L11, i22f = 1.f / L22, i33f = 1.f / L33;
                float i10f = -(L10 * i00f) * i11f;
                float i20f = -(L20 * i00f + L21 * i10f) * i22f;
                float i21f = -(L21 * i11f) * i22f;
                float i30f = -(L30 * i00f + L31 * i10f + L32 * i20f) * i33f;
                float i31f = -(L31 * i11f + L32 * i21f) * i33f;
                float i32f = -(L32 * i22f) * i33f;

                float Linv[4][4] = {{i00f, 0, 0, 0},
                                    {i10f, i11f, 0, 0},
                                    {i20f, i21f, i22f, 0},
                                    {i30f, i31f, i32f, i33f}};
                float m[4] = {m0, m1, m2, m3};
#pragma unroll
                for (int i = 0; i < 4; i++) {
                    float A[4];
#pragma unroll
                    for (int j = 0; j < 4; j++) {
                        float t2 = 0.f;
#pragma unroll
                        for (int k = 0; k < 4; k++)
                            if (k >= j) t2 = fmaf(weight[(i * 4 + k) * F_CH + f], Linv[k][j], t2);
                        A[j] = t2;
                        AC[i * 4 + j] = t2;
                    }
                    AC[16 + i] = bias[i * F_CH + f]
                               - (A[0] * m[0] + A[1] * m[1] + A[2] * m[2] + A[3] * m[3]);
                }
            }
        }
        __syncthreads();

        // ---- phase 2: mix from the smem tile, WT store ----
        float a00 = AC[0],  a01 = AC[1],  a02 = AC[2],  a03 = AC[3];
        float a10 = AC[4],  a11 = AC[5],  a12 = AC[6],  a13 = AC[7];
        float a20 = AC[8],  a21 = AC[9],  a22 = AC[10], a23 = AC[11];
        float a30 = AC[12], a31 = AC[13], a32 = AC[14], a33 = AC[15];
        float k0 = AC[16], k1 = AC[17], k2 = AC[18], k3 = AC[19];

        const size_t base = ((size_t)bb * 256 + f) * HW + (size_t)half * HALFN;
        float4* __restrict__ q0 = (float4*)(out + base);
        float4* __restrict__ q1 = (float4*)(out + base + (size_t)64  * HW);
        float4* __restrict__ q2 = (float4*)(out + base + (size_t)128 * HW);
        float4* __restrict__ q3 = (float4*)(out + base + (size_t)192 * HW);

#pragma unroll
        for (int rep = 0; rep < 2; rep++) {
            const int i = (rep == 0) ? i0 : i1;
            float4 v0 = b0[i], v1 = b1[i], v2 = b2[i], v3 = b3[i];
            st_wt4(q0 + i, mix4(v0, v1, v2, v3, a00, a01, a02, a03, k0));
            st_wt4(q1 + i, mix4(v0, v1, v2, v3, a10, a11, a12, a13, k1));
            st_wt4(q2 + i, mix4(v0, v1, v2, v3, a20, a21, a22, a23, k2));
            st_wt4(q3 + i, mix4(v0, v1, v2, v3, a30, a31, a32, a33, k3));
        }
        __syncthreads();   // tile/AC reuse safety before next round
    }
}

extern "C" void kernel_launch(void* const* d_in, const int* in_sizes, int n_in,
                              void* d_out, int out_size) {
    const float* x      = (const float*)d_in[0];
    const float* weight = (const float*)d_in[1];
    const float* bias   = (const float*)d_in[2];
    float* out = (float*)d_out;

    static int smem_set = 0;
    if (!smem_set) {
        cudaFuncSetAttribute(fused_qbn, cudaFuncAttributeMaxDynamicSharedMemorySize,
                             2 * BUF_FLT * (int)sizeof(float));
        smem_set = 1;
    }
    fused_qbn<<<NBLK, 256, 2 * BUF_FLT * sizeof(float)>>>(x, weight, bias, out);
}

// round 17
// speedup vs baseline: 1.9588x; 1.9588x over previous
#include <cuda_runtime.h>

#define F_CH   64
#define HW     4096
#define BATCH  32
#define NSTAT  14

__device__ float g_part[F_CH * BATCH * NSTAT];  // per-(f,b) partial stats

__device__ __forceinline__ void acc4(float x0, float x1, float x2, float x3, float* s) {
    s[0] += x0; s[1] += x1; s[2] += x2; s[3] += x3;
    s[4]  = fmaf(x0, x0, s[4]);
    s[5]  = fmaf(x0, x1, s[5]);
    s[6]  = fmaf(x0, x2, s[6]);
    s[7]  = fmaf(x0, x3, s[7]);
    s[8]  = fmaf(x1, x1, s[8]);
    s[9]  = fmaf(x1, x2, s[9]);
    s[10] = fmaf(x1, x3, s[10]);
    s[11] = fmaf(x2, x3, s[11]);
    s[12] = fmaf(x2, x2, s[12]);
    s[13] = fmaf(x3, x3, s[13]);
}
// s: 0..3 sums; 4:00 5:01 6:02 7:03 8:11 9:12 10:13 11:23 12:22 13:33

__device__ __forceinline__ void st_wt4(float4* p, float4 v) {
    asm volatile("st.global.wt.v4.f32 [%0], {%1,%2,%3,%4};"
                 :: "l"(p), "f"(v.x), "f"(v.y), "f"(v.z), "f"(v.w) : "memory");
}

// Pass 1: per-(f, batch) stats; signals dependent launch once partials are out.
__global__ __launch_bounds__(256) void pass1_stats(const float* __restrict__ x) {
    const int f = blockIdx.x;   // 0..63
    const int bb = blockIdx.y;  // 0..31
    const size_t base = ((size_t)bb * 256 + f) * HW;
    const float4* __restrict__ p0 = (const float4*)(x + base);
    const float4* __restrict__ p1 = (const float4*)(x + base + (size_t)64  * HW);
    const float4* __restrict__ p2 = (const float4*)(x + base + (size_t)128 * HW);
    const float4* __restrict__ p3 = (const float4*)(x + base + (size_t)192 * HW);

    float s[NSTAT];
#pragma unroll
    for (int k = 0; k < NSTAT; k++) s[k] = 0.f;

#pragma unroll
    for (int half = 0; half < 2; half++) {
        const int i0 = threadIdx.x + half * 512;
        const int i1 = i0 + 256;
        float4 a0 = __ldcg(p0 + i0);
        float4 b0 = __ldcg(p1 + i0);
        float4 c0 = __ldcg(p2 + i0);
        float4 d0 = __ldcg(p3 + i0);
        float4 a1 = __ldcg(p0 + i1);
        float4 b1 = __ldcg(p1 + i1);
        float4 c1 = __ldcg(p2 + i1);
        float4 d1 = __ldcg(p3 + i1);
        acc4(a0.x, b0.x, c0.x, d0.x, s);
        acc4(a0.y, b0.y, c0.y, d0.y, s);
        acc4(a0.z, b0.z, c0.z, d0.z, s);
        acc4(a0.w, b0.w, c0.w, d0.w, s);
        acc4(a1.x, b1.x, c1.x, d1.x, s);
        acc4(a1.y, b1.y, c1.y, d1.y, s);
        acc4(a1.z, b1.z, c1.z, d1.z, s);
        acc4(a1.w, b1.w, c1.w, d1.w, s);
    }

#pragma unroll
    for (int k = 0; k < NSTAT; k++) {
#pragma unroll
        for (int off = 16; off; off >>= 1)
            s[k] += __shfl_down_sync(0xffffffffu, s[k], off);
    }

    __shared__ float sm[8][NSTAT];
    const int warp = threadIdx.x >> 5, lane = threadIdx.x & 31;
    if (lane == 0) {
#pragma unroll
        for (int k = 0; k < NSTAT; k++) sm[warp][k] = s[k];
    }
    __syncthreads();
    if (threadIdx.x < NSTAT) {
        float t = 0.f;
#pragma unroll
        for (int w = 0; w < 8; w++) t += sm[w][threadIdx.x];
        g_part[(f * BATCH + bb) * NSTAT + threadIdx.x] = t;
        __threadfence();   // partials globally visible before the PDL trigger
    }
    __syncthreads();
    // PDL: this CTA's output is published; let pass2's grid begin launching.
    asm volatile("griddepcontrol.launch_dependents;");
}

__device__ __forceinline__ float4 mix4(float4 v0, float4 v1, float4 v2, float4 v3,
                                       float w0, float w1, float w2, float w3, float bb) {
    float4 o;
    o.x = fmaf(w0, v0.x, fmaf(w1, v1.x, fmaf(w2, v2.x, fmaf(w3, v3.x, bb))));
    o.y = fmaf(w0, v0.y, fmaf(w1, v1.y, fmaf(w2, v2.y, fmaf(w3, v3.y, bb))));
    o.z = fmaf(w0, v0.z, fmaf(w1, v1.z, fmaf(w2, v2.z, fmaf(w3, v3.z, bb))));
    o.w = fmaf(w0, v0.w, fmaf(w1, v1.w, fmaf(w2, v2.w, fmaf(w3, v3.w, bb))));
    return o;
}

// Pass 2 (PDL secondary): prefetch half-0 x reads BEFORE griddepcontrol.wait
// (they don't depend on pass1), then solve, then mix+store both halves.
__global__ __launch_bounds__(256) void pass2_apply(const float* __restrict__ x,
                                                   const float* __restrict__ weight,
                                                   const float* __restrict__ bias,
                                                   float* __restrict__ out) {
    const int rlin = (F_CH * BATCH - 1) - (blockIdx.y * F_CH + blockIdx.x);
    const int f  = rlin % F_CH;
    const int bb = rlin / F_CH;
    __shared__ float AC[20];

    const size_t base = ((size_t)bb * 256 + f) * HW;
    const float4* __restrict__ p0 = (const float4*)(x + base);
    const float4* __restrict__ p1 = (const float4*)(x + base + (size_t)64  * HW);
    const float4* __restrict__ p2 = (const float4*)(x + base + (size_t)128 * HW);
    const float4* __restrict__ p3 = (const float4*)(x + base + (size_t)192 * HW);

    // ---- prefetch half 0 (independent of pass1's output) ----
    const int i0a = threadIdx.x, i1a = threadIdx.x + 256;
    float4 v0 = __ldcg(p0 + i0a);
    float4 v1 = __ldcg(p1 + i0a);
    float4 v2 = __ldcg(p2 + i0a);
    float4 v3 = __ldcg(p3 + i0a);
    float4 w0 = __ldcg(p0 + i1a);
    float4 w1 = __ldcg(p1 + i1a);
    float4 w2 = __ldcg(p2 + i1a);
    float4 w3 = __ldcg(p3 + i1a);

    // ---- wait for pass1's grid (g_part visible after this) ----
    asm volatile("griddepcontrol.wait;" ::: "memory");

    if (threadIdx.x < 32) {
        const int lane = threadIdx.x;
        float s[NSTAT];
#pragma unroll
        for (int k = 0; k < NSTAT; k++) s[k] = g_part[(f * BATCH + lane) * NSTAT + k];
#pragma unroll
        for (int k = 0; k < NSTAT; k++) {
#pragma unroll
            for (int off = 16; off; off >>= 1)
                s[k] += __shfl_down_sync(0xffffffffu, s[k], off);
        }
        if (lane == 0) {
            const float invN = 1.0f / (float)(BATCH * HW);
            const float eps = 1e-5f;
            float m0 = s[0] * invN, m1 = s[1] * invN, m2 = s[2] * invN, m3 = s[3] * invN;
            float c00 = s[4]  * invN - m0 * m0 + eps;
            float c10 = s[5]  * invN - m0 * m1;
            float c20 = s[6]  * invN - m0 * m2;
            float c30 = s[7]  * invN - m0 * m3;
            float c11 = s[8]  * invN - m1 * m1 + eps;
            float c21 = s[9]  * invN - m1 * m2;
            float c31 = s[10] * invN - m1 * m3;
            float c32 = s[11] * invN - m2 * m3;
            float c22 = s[12] * invN - m2 * m2 + eps;
            float c33 = s[13] * invN - m3 * m3 + eps;

            float L00 = sqrtf(c00);
            float L10 = c10 / L00, L20 = c20 / L00, L30 = c30 / L00;
            float L11 = sqrtf(c11 - L10 * L10);
            float L21 = (c21 - L20 * L10) / L11;
            float L31 = (c31 - L30 * L10) / L11;
            float L22 = sqrtf(c22 - L20 * L20 - L21 * L21);
            float L32 = (c32 - L30 * L20 - L31 * L21) / L22;
            float L33 = sqrtf(c33 - L30 * L30 - L31 * L31 - L32 * L32);

            float i00 = 1.f / L00, i11 = 1.f / L11, i22 = 1.f / L22, i33 = 1.f / L33;
            float i10 = -(L10 * i00) * i11;
            float i20 = -(L20 * i00 + L21 * i10) * i22;
            float i21 = -(L21 * i11) * i22;
            float i30 = -(L30 * i00 + L31 * i10 + L32 * i20) * i33;
            float i31 = -(L31 * i11 + L32 * i21) * i33;
            float i32 = -(L32 * i22) * i33;

            float Linv[4][4] = {{i00, 0, 0, 0},
                                {i10, i11, 0, 0},
                                {i20, i21, i22, 0},
                                {i30, i31, i32, i33}};
            float m[4] = {m0, m1, m2, m3};
#pragma unroll
            for (int i = 0; i < 4; i++) {
                float A[4];
#pragma unroll
                for (int j = 0; j < 4; j++) {
                    float t = 0.f;
#pragma unroll
                    for (int k = 0; k < 4; k++)
                        if (k >= j) t = fmaf(weight[(i * 4 + k) * F_CH + f], Linv[k][j], t);
                    A[j] = t;
                    AC[i * 4 + j] = t;
                }
                AC[16 + i] = bias[i * F_CH + f]
                           - (A[0] * m[0] + A[1] * m[1] + A[2] * m[2] + A[3] * m[3]);
            }
        }
    }
    __syncthreads();

    float a00 = AC[0],  a01 = AC[1],  a02 = AC[2],  a03 = AC[3];
    float a10 = AC[4],  a11 = AC[5],  a12 = AC[6],  a13 = AC[7];
    float a20 = AC[8],  a21 = AC[9],  a22 = AC[10], a23 = AC[11];
    float a30 = AC[12], a31 = AC[13], a32 = AC[14], a33 = AC[15];
    float c0 = AC[16], c1 = AC[17], c2 = AC[18], c3 = AC[19];

    float4* __restrict__ q0 = (float4*)(out + base);
    float4* __restrict__ q1 = (float4*)(out + base + (size_t)64  * HW);
    float4* __restrict__ q2 = (float4*)(out + base + (size_t)128 * HW);
    float4* __restrict__ q3 = (float4*)(out + base + (size_t)192 * HW);

    // ---- half 0: use the prefetched tile ----
    st_wt4(q0 + i0a, mix4(v0, v1, v2, v3, a00, a01, a02, a03, c0));
    st_wt4(q1 + i0a, mix4(v0, v1, v2, v3, a10, a11, a12, a13, c1));
    st_wt4(q2 + i0a, mix4(v0, v1, v2, v3, a20, a21, a22, a23, c2));
    st_wt4(q3 + i0a, mix4(v0, v1, v2, v3, a30, a31, a32, a33, c3));
    st_wt4(q0 + i1a, mix4(w0, w1, w2, w3, a00, a01, a02, a03, c0));
    st_wt4(q1 + i1a, mix4(w0, w1, w2, w3, a10, a11, a12, a13, c1));
    st_wt4(q2 + i1a, mix4(w0, w1, w2, w3, a20, a21, a22, a23, c2));
    st_wt4(q3 + i1a, mix4(w0, w1, w2, w3, a30, a31, a32, a33, c3));

    // ---- half 1: load + mix + store ----
    const int i0b = threadIdx.x + 512, i1b = threadIdx.x + 768;
    {
        float4 u0 = __ldcg(p0 + i0b);
        float4 u1 = __ldcg(p1 + i0b);
        float4 u2 = __ldcg(p2 + i0b);
        float4 u3 = __ldcg(p3 + i0b);
        float4 z0 = __ldcg(p0 + i1b);
        float4 z1 = __ldcg(p1 + i1b);
        float4 z2 = __ldcg(p2 + i1b);
        float4 z3 = __ldcg(p3 + i1b);
        st_wt4(q0 + i0b, mix4(u0, u1, u2, u3, a00, a01, a02, a03, c0));
        st_wt4(q1 + i0b, mix4(u0, u1, u2, u3, a10, a11, a12, a13, c1));
        st_wt4(q2 + i0b, mix4(u0, u1, u2, u3, a20, a21, a22, a23, c2));
        st_wt4(q3 + i0b, mix4(u0, u1, u2, u3, a30, a31, a32, a33, c3));
        st_wt4(q0 + i1b, mix4(z0, z1, z2, z3, a00, a01, a02, a03, c0));
        st_wt4(q1 + i1b, mix4(z0, z1, z2, z3, a10, a11, a12, a13, c1));
        st_wt4(q2 + i1b, mix4(z0, z1, z2, z3, a20, a21, a22, a23, c2));
        st_wt4(q3 + i1b, mix4(z0, z1, z2, z3, a30, a31, a32, a33, c3));
    }
}

extern "C" void kernel_launch(void* const* d_in, const int* in_sizes, int n_in,
                              void* d_out, int out_size) {
    const float* x      = (const float*)d_in[0];
    const float* weight = (const float*)d_in[1];
    const float* bias   = (const float*)d_in[2];
    float* out = (float*)d_out;

    dim3 grid(F_CH, BATCH);
    pass1_stats<<<grid, 256>>>(x);

    // Launch pass2 as a PDL secondary: it may begin launching as soon as all
    // pass1 CTAs have executed griddepcontrol.launch_dependents.
    cudaLaunchConfig_t cfg = {};
    cfg.gridDim = grid;
    cfg.blockDim = dim3(256, 1, 1);
    cfg.dynamicSmemBytes = 0;
    cfg.stream = 0;
    cudaLaunchAttribute attr[1];
    attr[0].id = cudaLaunchAttributeProgrammaticStreamSerialization;
    attr[0].val.programmaticStreamSerializationAllowed = 1;
    cfg.attrs = attr;
    cfg.numAttrs = 1;
    cudaLaunchKernelEx(&cfg, pass2_apply, x, weight, bias, out);
}